// round 12
// baseline (speedup 1.0000x reference)
#include <cuda_runtime.h>

// Problem shape (fixed by setup_inputs):
//   x1: [B=32, C=64, h=42, w=42]       float32
//   x2: [B=32, S=25, C=64, h=42, w=42] float32
//   out: [B, S*h*w] = [32, 44100]      float32
// out[b, s*HW + p] = sqrt( sum_c (x1[b,c,p] - x2[b,s,c,p])^2 )
//
// Asymmetric-depth register pipeline, fine-grained (2 channels/stage):
//   x2 (DRAM stream): prefetch distance 8 -> 16 loads continuously in flight
//   x1 (L2-resident): prefetch distance 2 -> 4 loads in flight
// Same register/occupancy budget as the distance-3 version; pure depth gain
// on the stream that actually hits DRAM.

#define B_  32
#define S_  25
#define C_  64
#define HW_ 1764          // 42*42
#define HW4_ 441          // HW/4 (exact)
#define TOTAL_ (B_ * S_ * HW4_)   // 352800 threads, one float4 output each

#define CB_ 2                      // channels per pipeline stage
#define NSTAGE_ (C_ / CB_)         // 32 stages
#define NBUF2_ 9                   // x2 buffers (prefetch distance 8)
#define NBUF1_ 3                   // x1 buffers (prefetch distance 2)

__global__ __launch_bounds__(256, 2)
void euclidean_block_kernel(const float* __restrict__ x1,
                            const float* __restrict__ x2,
                            float* __restrict__ out) {
    int t = blockIdx.x * blockDim.x + threadIdx.x;
    if (t >= TOTAL_) return;

    int p4 = t % HW4_;          // which float4 within the 1764-pixel plane
    int bs = t / HW4_;          // (b*S + s)
    int b  = bs / S_;

    const float4* __restrict__ x1p =
        reinterpret_cast<const float4*>(x1 + (size_t)b * C_ * HW_) + p4;
    const float4* __restrict__ x2p =
        reinterpret_cast<const float4*>(x2 + (size_t)bs * C_ * HW_) + p4;

    float ax = 0.f, ay = 0.f, az = 0.f, aw = 0.f;

    float4 v[NBUF2_][CB_];   // x2: deep (72 regs)
    float4 a[NBUF1_][CB_];   // x1: shallow (24 regs)

    // Prologue: x2 stages 0..7 in flight; x1 stages 0..1 in flight.
    #pragma unroll
    for (int s = 0; s < NBUF2_ - 1; ++s) {
        #pragma unroll
        for (int i = 0; i < CB_; ++i)
            v[s][i] = __ldcs(&x2p[(s * CB_ + i) * HW4_]);
    }
    #pragma unroll
    for (int s = 0; s < NBUF1_ - 1; ++s) {
        #pragma unroll
        for (int i = 0; i < CB_; ++i)
            a[s][i] = x1p[(s * CB_ + i) * HW4_];
    }

    #pragma unroll
    for (int s = 0; s < NSTAGE_; ++s) {
        // Prefetch x2 stage s+8 (keeps 16 x2 loads outstanding at all times).
        if (s + NBUF2_ - 1 < NSTAGE_) {
            const int pf = (s + NBUF2_ - 1) % NBUF2_;
            const int c0 = (s + NBUF2_ - 1) * CB_;
            #pragma unroll
            for (int i = 0; i < CB_; ++i)
                v[pf][i] = __ldcs(&x2p[(c0 + i) * HW4_]);
        }
        // Prefetch x1 stage s+2 (L2 hit; short distance suffices).
        if (s + NBUF1_ - 1 < NSTAGE_) {
            const int pf = (s + NBUF1_ - 1) % NBUF1_;
            const int c0 = (s + NBUF1_ - 1) * CB_;
            #pragma unroll
            for (int i = 0; i < CB_; ++i)
                a[pf][i] = x1p[(c0 + i) * HW4_];
        }

        // Consume stage s.
        const int c2 = s % NBUF2_;
        const int c1 = s % NBUF1_;
        #pragma unroll
        for (int i = 0; i < CB_; ++i) {
            float d0 = a[c1][i].x - v[c2][i].x;
            float d1 = a[c1][i].y - v[c2][i].y;
            float d2 = a[c1][i].z - v[c2][i].z;
            float d3 = a[c1][i].w - v[c2][i].w;
            ax = fmaf(d0, d0, ax);
            ay = fmaf(d1, d1, ay);
            az = fmaf(d2, d2, az);
            aw = fmaf(d3, d3, aw);
        }
    }

    float4 r;
    r.x = sqrtf(ax);
    r.y = sqrtf(ay);
    r.z = sqrtf(az);
    r.w = sqrtf(aw);

    reinterpret_cast<float4*>(out)[(size_t)bs * HW4_ + p4] = r;
}

extern "C" void kernel_launch(void* const* d_in, const int* in_sizes, int n_in,
                              void* d_out, int out_size) {
    const float* x1 = (const float*)d_in[0];
    const float* x2 = (const float*)d_in[1];
    float* out = (float*)d_out;

    const int threads = 256;
    const int blocks = (TOTAL_ + threads - 1) / threads;  // 1379, flat grid
    euclidean_block_kernel<<<blocks, threads>>>(x1, x2, out);
}